// round 9
// baseline (speedup 1.0000x reference)
#include <cuda_runtime.h>
#include <cuda_bf16.h>
#include <cuda_fp16.h>
#include <cstdint>

// Problem constants
#define NB 8       // batch
#define NC 256     // channels
#define NN 4096    // H*W
#define ND 8       // d_qk
#define BM 128     // query rows per CTA (flash)
#define BN2 64     // key tile
#define NTILES (NN / BN2)
#define LOG2E 1.4426950408889634f

typedef unsigned long long u64;
typedef unsigned int u32;

// Scratch (device globals; allocation APIs are forbidden)
__device__ float g_q[NB * NN * ND];                   // [b][n][d]
__device__ float g_k[NB * NN * ND];                   // [b][n][d]
__device__ __nv_bfloat16 g_v[(size_t)NB * NC * NN];   // [b][c][n]

// ---------------- helpers ----------------
// pack bf16x2: lower 16 bits = first arg
__device__ __forceinline__ u32 bf2(float lo, float hi) {
    u32 r; asm("cvt.rn.bf16x2.f32 %0, %1, %2;" : "=r"(r) : "f"(hi), "f"(lo)); return r;
}
__device__ __forceinline__ float bflo(u32 w) { return __uint_as_float(w << 16); }
__device__ __forceinline__ float bfhi(u32 w) { return __uint_as_float(w & 0xffff0000u); }
__device__ __forceinline__ float ex2f(float x) {
    float r; asm("ex2.approx.f32 %0, %1;" : "=f"(r) : "f"(x)); return r;
}
__device__ __forceinline__ u32 smem_u32(const void* p) {
    u32 a; asm("{ .reg .u64 t; cvta.to.shared.u64 t, %1; cvt.u32.u64 %0, t; }" : "=r"(a) : "l"(p));
    return a;
}
__device__ __forceinline__ void cpa16(u32 dst, const void* src) {
    asm volatile("cp.async.cg.shared.global [%0], [%1], 16;" :: "r"(dst), "l"(src));
}
__device__ __forceinline__ void ldmx4(u32 a, u32 &r0, u32 &r1, u32 &r2, u32 &r3) {
    asm volatile("ldmatrix.sync.aligned.m8n8.x4.shared.b16 {%0,%1,%2,%3}, [%4];"
                 : "=r"(r0), "=r"(r1), "=r"(r2), "=r"(r3) : "r"(a));
}
__device__ __forceinline__ void ldmx2(u32 a, u32 &r0, u32 &r1) {
    asm volatile("ldmatrix.sync.aligned.m8n8.x2.shared.b16 {%0,%1}, [%2];"
                 : "=r"(r0), "=r"(r1) : "r"(a));
}
__device__ __forceinline__ void ldmx2t(u32 a, u32 &r0, u32 &r1) {
    asm volatile("ldmatrix.sync.aligned.m8n8.x2.trans.shared.b16 {%0,%1}, [%2];"
                 : "=r"(r0), "=r"(r1) : "r"(a));
}
__device__ __forceinline__ void mma16816(float* d, u32 a0, u32 a1, u32 a2, u32 a3,
                                         u32 b0, u32 b1) {
    asm volatile(
        "mma.sync.aligned.m16n8k16.row.col.f32.bf16.bf16.f32 "
        "{%0,%1,%2,%3}, {%4,%5,%6,%7}, {%8,%9}, {%0,%1,%2,%3};"
        : "+f"(d[0]), "+f"(d[1]), "+f"(d[2]), "+f"(d[3])
        : "r"(a0), "r"(a1), "r"(a2), "r"(a3), "r"(b0), "r"(b1));
}

// ---------------------------------------------------------------------------
// Kernel 1 (fused): V projection + Q/K projection via HMMA (R7-passing).
// ---------------------------------------------------------------------------
#define PW_H   0                      // [272][64] bf16 = 34816 B
#define PW_L   34816                  // [272][64] bf16
#define PX_H   69632                  // [64][128] bf16 = 16384 B
#define PX_L   86016                  // [64][128] bf16
#define PBV    102400                 // 256 f32 = 1024 B
#define PROJ_SMEM 103424
#define PSTAGE 0                      // epilogue stage reuses W area (64 KB)

__global__ __launch_bounds__(256, 1) void proj_kernel(
    const float* __restrict__ x,
    const float* __restrict__ wq, const float* __restrict__ bq,
    const float* __restrict__ wk, const float* __restrict__ bk,
    const float* __restrict__ wv, const float* __restrict__ bv)
{
    extern __shared__ char sm[];
    u32 sb = smem_u32(sm);
    int t = threadIdx.x, l = t & 31, w = t >> 5;
    int b = blockIdx.y, n0 = blockIdx.x * 128;
    int co_blk = (w & 3) * 64, n_blk = (w >> 2) * 64;

    float* sBV = (float*)(sm + PBV);
    if (t < 256) sBV[t] = bv[t];

    float acc[128];
#pragma unroll
    for (int i = 0; i < 128; i++) acc[i] = 0.0f;
    float qacc[2][4];
#pragma unroll
    for (int i = 0; i < 2; i++)
#pragma unroll
        for (int jj = 0; jj < 4; jj++) qacc[i][jj] = 0.0f;

    int arow = co_blk + (l & 15);
    int qrow = 256 + (l & 15);
    u32 acolh = (u32)((l >> 4) << 4);

    for (int ch = 0; ch < 4; ch++) {
        int c0 = ch * 64;
#pragma unroll
        for (int e = 0; e < 17; e++) {
            int i = t + 256 * e;
            int row = i >> 4, f4 = i & 15;
            const float* src;
            if (row < 256)      src = wv + (size_t)row * NC + c0;
            else if (row < 264) src = wq + (size_t)(row - 256) * NC + c0;
            else                src = wk + (size_t)(row - 264) * NC + c0;
            float4 v4 = *(const float4*)(src + f4 * 4);
            u32 h0 = bf2(v4.x, v4.y), h1 = bf2(v4.z, v4.w);
            u32 l0 = bf2(v4.x - bflo(h0), v4.y - bfhi(h0));
            u32 l1 = bf2(v4.z - bflo(h1), v4.w - bfhi(h1));
            u32 off = (u32)(row * 128) + (u32)((f4 * 8) ^ ((row & 7) << 4));
            *(uint2*)(sm + PW_H + off) = make_uint2(h0, h1);
            *(uint2*)(sm + PW_L + off) = make_uint2(l0, l1);
        }
#pragma unroll
        for (int e = 0; e < 8; e++) {
            int i = t + 256 * e;
            int row = i >> 5, n4 = (i & 31) * 4;
            float4 v4 = *(const float4*)(x + ((size_t)b * NC + c0 + row) * NN + n0 + n4);
            u32 h0 = bf2(v4.x, v4.y), h1 = bf2(v4.z, v4.w);
            u32 l0 = bf2(v4.x - bflo(h0), v4.y - bfhi(h0));
            u32 l1 = bf2(v4.z - bflo(h1), v4.w - bfhi(h1));
            u32 off = (u32)(row * 256) + (u32)((n4 * 2) ^ ((row & 7) << 4));
            *(uint2*)(sm + PX_H + off) = make_uint2(h0, h1);
            *(uint2*)(sm + PX_L + off) = make_uint2(l0, l1);
        }
        __syncthreads();

#pragma unroll
        for (int kt = 0; kt < 4; kt++) {
            u32 kb = (u32)(kt * 32);
            u32 ah[4][4], al[4][4];
#pragma unroll
            for (int mt = 0; mt < 4; mt++) {
                int rr = arow + mt * 16;
                u32 ad = (u32)(rr * 128) + ((kb + acolh) ^ (u32)((rr & 7) << 4));
                ldmx4(sb + PW_H + ad, ah[mt][0], ah[mt][1], ah[mt][2], ah[mt][3]);
                ldmx4(sb + PW_L + ad, al[mt][0], al[mt][1], al[mt][2], al[mt][3]);
            }
#pragma unroll
            for (int nt = 0; nt < 8; nt++) {
                int cir = kt * 16 + (l & 15);
                u32 bd = sb + PX_H + (u32)(cir * 256)
                       + (u32)(((n_blk + nt * 8) * 2) ^ ((cir & 7) << 4));
                u32 b0, b1;
                ldmx2t(bd, b0, b1);
#pragma unroll
                for (int mt = 0; mt < 4; mt++) {
                    float* d = &acc[(mt * 8 + nt) * 4];
                    mma16816(d, ah[mt][0], ah[mt][1], ah[mt][2], ah[mt][3], b0, b1);
                    mma16816(d, al[mt][0], al[mt][1], al[mt][2], al[mt][3], b0, b1);
                }
            }
            {
                int rr = qrow;
                u32 ad = (u32)(rr * 128) + ((kb + acolh) ^ (u32)((rr & 7) << 4));
                u32 qh[4], ql[4];
                ldmx4(sb + PW_H + ad, qh[0], qh[1], qh[2], qh[3]);
                ldmx4(sb + PW_L + ad, ql[0], ql[1], ql[2], ql[3]);
                int cir = kt * 16 + (l & 15);
                u32 rswz = (u32)((cir & 7) << 4);
                u32 rbase = (u32)(cir * 256);
#pragma unroll
                for (int qi = 0; qi < 2; qi++) {
                    int qnt = 2 * w + qi;
                    u32 cbyte = (u32)((qnt * 8) * 2) ^ rswz;
                    u32 bh0, bh1, bl0, bl1;
                    ldmx2t(sb + PX_H + rbase + cbyte, bh0, bh1);
                    ldmx2t(sb + PX_L + rbase + cbyte, bl0, bl1);
                    mma16816(qacc[qi], qh[0], qh[1], qh[2], qh[3], bh0, bh1);
                    mma16816(qacc[qi], qh[0], qh[1], qh[2], qh[3], bl0, bl1);
                    mma16816(qacc[qi], ql[0], ql[1], ql[2], ql[3], bh0, bh1);
                }
            }
        }
        __syncthreads();
    }

    {
        int d_ = l >> 2;
        float bq_ = bq[d_], bk_ = bk[d_];
#pragma unroll
        for (int qi = 0; qi < 2; qi++) {
            int n_g = n0 + (2 * w + qi) * 8 + (l & 3) * 2;
            size_t e0 = ((size_t)b * NN + n_g) * ND + d_;
            g_q[e0]      = qacc[qi][0] + bq_;
            g_q[e0 + ND] = qacc[qi][1] + bq_;
            g_k[e0]      = qacc[qi][2] + bk_;
            g_k[e0 + ND] = qacc[qi][3] + bk_;
        }
    }

    {
        char* stg = sm + PSTAGE + w * 8192;  // [64 co][64 n] bf16, swizzled
#pragma unroll
        for (int mt = 0; mt < 4; mt++) {
            int r0 = mt * 16 + (l >> 2);
            float b0_ = sBV[co_blk + r0];
            float b1_ = sBV[co_blk + r0 + 8];
#pragma unroll
            for (int nt = 0; nt < 8; nt++) {
                const float* d = &acc[(mt * 8 + nt) * 4];
                u32 w0 = bf2(d[0] + b0_, d[1] + b0_);
                u32 w1 = bf2(d[2] + b1_, d[3] + b1_);
                u32 cb = (u32)(nt * 16 + (l & 3) * 4);
                *(u32*)(stg + r0 * 128 + (cb ^ ((r0 & 7) << 4))) = w0;
                *(u32*)(stg + (r0 + 8) * 128 + (cb ^ (((r0 + 8) & 7) << 4))) = w1;
            }
        }
    }
    __syncthreads();
#pragma unroll
    for (int e = 0; e < 16; e++) {
        int i = t + 256 * e;
        int co = i >> 4, chn = i & 15;
        int n = chn * 8;
        int wr = (co >> 6) | ((n >> 6) << 2);
        int cr = co & 63, nr = n & 63;
        float4 v4 = *(const float4*)(sm + PSTAGE + wr * 8192 + cr * 128
                                     + ((nr * 2) ^ ((cr & 7) << 4)));
        *(float4*)((void*)(g_v + ((size_t)b * NC + co) * NN + n0 + n)) = v4;
    }
}

// ---------------------------------------------------------------------------
// Kernel 2: flash attention. R8 change: ONE barrier per tile; P and K double
// buffered so sphase(j+1) overlaps PV(j) across warps (tensor pipe stays fed).
// ---------------------------------------------------------------------------
#define OFF_K   0                     // 2 x [64][32] bf16 hi/lo = 4096 B
#define OFF_P   4096                  // 2 x [128][64] bf16 = 32768 B
#define OFF_V   36864                 // 2 x [256][64] bf16 = 65536 B
#define OFF_RS  102400                // 256 f32 = 1024 B
#define FLASH_SMEM 103424

__global__ __launch_bounds__(256, 1) void flash_mma_kernel(
    const float* __restrict__ x,
    const float* __restrict__ gamma,
    float* __restrict__ out)
{
    extern __shared__ char sm[];
    u32 sb = smem_u32(sm);
    int t = threadIdx.x, l = t & 31, w = t >> 5;
    int b = blockIdx.y, m0 = blockIdx.x * BM;
    int m_blk = (w >> 2) * 64, c_blk = (w & 3) * 64;
    int r = l >> 2, c2 = (l & 3) * 2;

    // ---- Q fragments: hi/lo bf16, log2e folded ----
    u32 qa0, qa1, qa2, qa3;
    {
        int qrow = m0 + w * 16 + r;
        const float* qp = g_q + ((size_t)b * NN + qrow) * ND + c2;
        const float* qp2 = qp + 8 * ND;
        float x0 = qp[0] * LOG2E, x1 = qp[1] * LOG2E;
        float y0 = qp2[0] * LOG2E, y1 = qp2[1] * LOG2E;
        qa0 = bf2(x0, x1);
        qa1 = bf2(y0, y1);
        qa2 = bf2(x0 - bflo(qa0), x1 - bfhi(qa0));
        qa3 = bf2(y0 - bflo(qa1), y1 - bfhi(qa1));
    }

    float acc[128];
#pragma unroll
    for (int i = 0; i < 128; i++) acc[i] = 0.0f;
    float lsA = 0.0f, lsB = 0.0f;

    const __nv_bfloat16* vg = g_v + (size_t)b * NC * NN;

    u32 pbase = sb + OFF_P, vbase = sb + OFF_V;
    int arow  = m_blk + (l & 15);
    u32 aswz  = (u32)((l & 7) << 4);
    u32 acolh = (u32)((l >> 4) << 4);
    int brow_l = l & 7;
    u32 bkh   = (u32)(((l >> 3) & 1) << 4);

    float4 kA, kB;  // K register staging (threads 0..63)

    auto ldgK = [&](int j) {
        if (t < 64) {
            const float4* kp = (const float4*)(g_k + ((size_t)b * NN + j * BN2 + t) * ND);
            kA = kp[0]; kB = kp[1];
        }
    };
    auto stsK = [&](int kbuf) {
        if (t < 64) {
            uint4 hi, lo;
            hi.x = bf2(kA.x, kA.y); hi.y = bf2(kA.z, kA.w);
            hi.z = bf2(kB.x, kB.y); hi.w = bf2(kB.z, kB.w);
            lo.x = bf2(kA.x - bflo(hi.x), kA.y - bfhi(hi.x));
            lo.y = bf2(kA.z - bflo(hi.y), kA.w - bfhi(hi.y));
            lo.z = bf2(kB.x - bflo(hi.z), kB.y - bfhi(hi.z));
            lo.w = bf2(kB.z - bflo(hi.w), kB.w - bfhi(hi.w));
            u32 sw = (u32)((t & 4) << 2);
            char* kd = sm + OFF_K + kbuf * 2048;
            *(uint4*)(kd + t * 32 + sw) = hi;
            *(uint4*)(kd + t * 32 + (16u ^ sw)) = lo;
        }
    };
    auto loadV = [&](int j, int buf) {
        u32 vd = vbase + (u32)buf * 32768;
        const __nv_bfloat16* vsrc = vg + j * BN2;
#pragma unroll
        for (int e = 0; e < 8; e++) {
            int lin = e * 256 + t;
            int row = lin >> 3, c16 = lin & 7;
            u32 dof = (u32)(row * 128 + ((c16 * 16) ^ ((row & 7) << 4)));
            cpa16(vd + dof, vsrc + (size_t)row * NN + c16 * 8);
        }
        asm volatile("cp.async.commit_group;" ::: "memory");
    };
    // S phase for tile j -> P[pbuf], reads K[pbuf]
    auto sphase = [&](int pbuf) {
        int rowa = w * 16 + r;
        u32 paxor = (u32)((rowa & 7) << 4);
        u32 pcol  = (u32)((l & 3) * 4);
        char* pd = sm + OFF_P + pbuf * 16384;
        char* prow0 = pd + rowa * 128;
        char* prow8 = prow0 + 8 * 128;
        u32 kbase = sb + OFF_K + (u32)pbuf * 2048;
#pragma unroll
        for (int nt = 0; nt < 8; nt++) {
            u32 krow = (u32)(nt * 8 + (l & 7));
            u32 ksw  = (krow & 4) << 2;
            u32 ka   = kbase + krow * 32;
            u32 bh0, bh1, bl0, bl1;
            ldmx2(ka + ksw, bh0, bh1);
            ldmx2(ka + (16u ^ ksw), bl0, bl1);
            float ds[4] = {0.f, 0.f, 0.f, 0.f};
            mma16816(ds, qa0, qa1, qa2, qa3, bh0, bh1);
            mma16816(ds, qa0, qa1, qa2, qa3, bl0, bl1);
            u32 p01 = bf2(ex2f(ds[0]), ex2f(ds[1]));
            u32 p23 = bf2(ex2f(ds[2]), ex2f(ds[3]));
            lsA += bflo(p01) + bfhi(p01);
            lsB += bflo(p23) + bfhi(p23);
            u32 cbyte = ((u32)(nt * 16) + pcol) ^ paxor;
            *(u32*)(prow0 + cbyte) = p01;
            *(u32*)(prow8 + cbyte) = p23;
        }
    };

    // ---- prologue: K0,V0 in; sphase(0); K1 staged ----
    ldgK(0); stsK(0); loadV(0, 0);
    ldgK(1);
    asm volatile("cp.async.wait_group 0;" ::: "memory");
    __syncthreads();                  // K0, V0 visible
    sphase(0);                        // P0 (buf 0)
    stsK(1);                          // K1 -> buf 1
    __syncthreads();                  // P0, K1 visible

    for (int j = 0; j < NTILES; j++) {
        int buf = j & 1;
        if (j + 2 < NTILES) ldgK(j + 2);
        if (j + 1 < NTILES) loadV(j + 1, buf ^ 1);

        // ---- PV MMA(j): reads P[buf], V[buf] ----
        u32 pb = pbase + (u32)buf * 16384;
        u32 vb = vbase + (u32)buf * 32768;
#pragma unroll
        for (int ks = 0; ks < 4; ks++) {
            u32 af[4][4];
#pragma unroll
            for (int mt = 0; mt < 4; mt++) {
                u32 ad = pb + (u32)((arow + mt * 16) * 128)
                       + (((u32)(ks * 32) + acolh) ^ aswz);
                ldmx4(ad, af[mt][0], af[mt][1], af[mt][2], af[mt][3]);
            }
#pragma unroll
            for (int ct = 0; ct < 8; ct++) {
                u32 brel = (u32)((c_blk + ct * 8 + brow_l) * 128)
                         + (((u32)(ks * 32) + bkh) ^ ((u32)brow_l << 4));
                u32 b0, b1;
                ldmx2(vb + brel, b0, b1);
#pragma unroll
                for (int mt = 0; mt < 4; mt++)
                    mma16816(&acc[(mt * 8 + ct) * 4],
                             af[mt][0], af[mt][1], af[mt][2], af[mt][3], b0, b1);
            }
        }

        // ---- sphase(j+1): writes P[buf^1], reads K[buf^1] ----
        if (j + 1 < NTILES) sphase(buf ^ 1);
        // ---- stage K(j+2) into K[buf] (last read pre-barrier by sphase(j)) ----
        if (j + 2 < NTILES) stsK(buf);

        asm volatile("cp.async.wait_group 0;" ::: "memory");
        __syncthreads();   // P(j+1), V(j+1), K(j+2) visible; P(j)/V(j) free
    }

    lsA += __shfl_xor_sync(0xffffffffu, lsA, 1);
    lsA += __shfl_xor_sync(0xffffffffu, lsA, 2);
    lsB += __shfl_xor_sync(0xffffffffu, lsB, 1);
    lsB += __shfl_xor_sync(0xffffffffu, lsB, 2);
    float* rs = (float*)(sm + OFF_RS);
    if ((l & 3) == 0) {
        rs[w * 16 + r]     = lsA;
        rs[w * 16 + r + 8] = lsB;
    }
    __syncthreads();
    if (t < 128) rs[t] = 1.0f / rs[t];
    __syncthreads();

    float gm = *gamma;

#pragma unroll
    for (int mt = 0; mt < 4; mt++) {
        int r0 = m_blk + mt * 16 + (l >> 2);
        float s0 = gm * rs[r0];
        float s1 = gm * rs[r0 + 8];
#pragma unroll
        for (int ct = 0; ct < 8; ct++) {
            int c0 = c_blk + ct * 8 + (l & 3) * 2;
            const float* d = &acc[(mt * 8 + ct) * 4];
            size_t a0 = ((size_t)(b * NC + c0)) * NN + m0 + r0;
            size_t a1 = a0 + NN;
            out[a0]     = d[0] * s0 + x[a0];
            out[a1]     = d[1] * s0 + x[a1];
            out[a0 + 8] = d[2] * s1 + x[a0 + 8];
            out[a1 + 8] = d[3] * s1 + x[a1 + 8];
        }
    }
}

// ---------------------------------------------------------------------------
extern "C" void kernel_launch(void* const* d_in, const int* in_sizes, int n_in,
                              void* d_out, int out_size)
{
    const float* x     = (const float*)d_in[0];
    const float* wq    = (const float*)d_in[1];
    const float* bq    = (const float*)d_in[2];
    const float* wk    = (const float*)d_in[3];
    const float* bk    = (const float*)d_in[4];
    const float* wv    = (const float*)d_in[5];
    const float* bv    = (const float*)d_in[6];
    const float* gamma = (const float*)d_in[7];
    float* out = (float*)d_out;

    cudaFuncSetAttribute(proj_kernel,
                         cudaFuncAttributeMaxDynamicSharedMemorySize,
                         PROJ_SMEM);
    cudaFuncSetAttribute(flash_mma_kernel,
                         cudaFuncAttributeMaxDynamicSharedMemorySize,
                         FLASH_SMEM);

    proj_kernel<<<dim3(NN / 128, NB), 256, PROJ_SMEM>>>(x, wq, bq, wk, bk, wv, bv);
    flash_mma_kernel<<<dim3(NN / BM, NB), 256, FLASH_SMEM>>>(x, gamma, out);
}

// round 10
// speedup vs baseline: 1.1023x; 1.1023x over previous
#include <cuda_runtime.h>
#include <cuda_bf16.h>
#include <cuda_fp16.h>
#include <cstdint>

// Problem constants
#define NB 8       // batch
#define NC 256     // channels
#define NN 4096    // H*W
#define ND 8       // d_qk
#define BM 128     // query rows per CTA (flash)
#define BN2 64     // key tile
#define NTILES (NN / BN2)
#define LOG2E 1.4426950408889634f

typedef unsigned long long u64;
typedef unsigned int u32;

// Scratch (device globals; allocation APIs are forbidden)
__device__ float g_q[NB * NN * ND];                   // [b][n][d]
__device__ float g_k[NB * NN * ND];                   // [b][n][d]
__device__ __nv_bfloat16 g_v[(size_t)NB * NC * NN];   // [b][c][n]

// ---------------- helpers ----------------
// pack bf16x2: lower 16 bits = first arg
__device__ __forceinline__ u32 bf2(float lo, float hi) {
    u32 r; asm("cvt.rn.bf16x2.f32 %0, %1, %2;" : "=r"(r) : "f"(hi), "f"(lo)); return r;
}
// pack fp16x2: lower 16 bits = first arg
__device__ __forceinline__ u32 f16x2(float lo, float hi) {
    u32 r; asm("cvt.rn.f16x2.f32 %0, %1, %2;" : "=r"(r) : "f"(hi), "f"(lo)); return r;
}
__device__ __forceinline__ float bflo(u32 w) { return __uint_as_float(w << 16); }
__device__ __forceinline__ float bfhi(u32 w) { return __uint_as_float(w & 0xffff0000u); }
__device__ __forceinline__ float ex2f(float x) {
    float r; asm("ex2.approx.f32 %0, %1;" : "=f"(r) : "f"(x)); return r;
}
__device__ __forceinline__ u32 smem_u32(const void* p) {
    u32 a; asm("{ .reg .u64 t; cvta.to.shared.u64 t, %1; cvt.u32.u64 %0, t; }" : "=r"(a) : "l"(p));
    return a;
}
__device__ __forceinline__ void cpa16(u32 dst, const void* src) {
    asm volatile("cp.async.cg.shared.global [%0], [%1], 16;" :: "r"(dst), "l"(src));
}
__device__ __forceinline__ void ldmx4(u32 a, u32 &r0, u32 &r1, u32 &r2, u32 &r3) {
    asm volatile("ldmatrix.sync.aligned.m8n8.x4.shared.b16 {%0,%1,%2,%3}, [%4];"
                 : "=r"(r0), "=r"(r1), "=r"(r2), "=r"(r3) : "r"(a));
}
__device__ __forceinline__ void ldmx2(u32 a, u32 &r0, u32 &r1) {
    asm volatile("ldmatrix.sync.aligned.m8n8.x2.shared.b16 {%0,%1}, [%2];"
                 : "=r"(r0), "=r"(r1) : "r"(a));
}
__device__ __forceinline__ void ldmx2t(u32 a, u32 &r0, u32 &r1) {
    asm volatile("ldmatrix.sync.aligned.m8n8.x2.trans.shared.b16 {%0,%1}, [%2];"
                 : "=r"(r0), "=r"(r1) : "r"(a));
}
__device__ __forceinline__ void mma16816(float* d, u32 a0, u32 a1, u32 a2, u32 a3,
                                         u32 b0, u32 b1) {
    asm volatile(
        "mma.sync.aligned.m16n8k16.row.col.f32.bf16.bf16.f32 "
        "{%0,%1,%2,%3}, {%4,%5,%6,%7}, {%8,%9}, {%0,%1,%2,%3};"
        : "+f"(d[0]), "+f"(d[1]), "+f"(d[2]), "+f"(d[3])
        : "r"(a0), "r"(a1), "r"(a2), "r"(a3), "r"(b0), "r"(b1));
}
__device__ __forceinline__ void mma16816f(float* d, u32 a0, u32 a1, u32 a2, u32 a3,
                                          u32 b0, u32 b1) {
    asm volatile(
        "mma.sync.aligned.m16n8k16.row.col.f32.f16.f16.f32 "
        "{%0,%1,%2,%3}, {%4,%5,%6,%7}, {%8,%9}, {%0,%1,%2,%3};"
        : "+f"(d[0]), "+f"(d[1]), "+f"(d[2]), "+f"(d[3])
        : "r"(a0), "r"(a1), "r"(a2), "r"(a3), "r"(b0), "r"(b1));
}

// ---------------------------------------------------------------------------
// Kernel 1 (fused): V projection + Q/K projection via HMMA (R7-passing).
// ---------------------------------------------------------------------------
#define PW_H   0                      // [272][64] bf16 = 34816 B
#define PW_L   34816                  // [272][64] bf16
#define PX_H   69632                  // [64][128] bf16 = 16384 B
#define PX_L   86016                  // [64][128] bf16
#define PBV    102400                 // 256 f32 = 1024 B
#define PROJ_SMEM 103424
#define PSTAGE 0                      // epilogue stage reuses W area (64 KB)

__global__ __launch_bounds__(256, 1) void proj_kernel(
    const float* __restrict__ x,
    const float* __restrict__ wq, const float* __restrict__ bq,
    const float* __restrict__ wk, const float* __restrict__ bk,
    const float* __restrict__ wv, const float* __restrict__ bv)
{
    extern __shared__ char sm[];
    u32 sb = smem_u32(sm);
    int t = threadIdx.x, l = t & 31, w = t >> 5;
    int b = blockIdx.y, n0 = blockIdx.x * 128;
    int co_blk = (w & 3) * 64, n_blk = (w >> 2) * 64;

    float* sBV = (float*)(sm + PBV);
    if (t < 256) sBV[t] = bv[t];

    float acc[128];
#pragma unroll
    for (int i = 0; i < 128; i++) acc[i] = 0.0f;
    float qacc[2][4];
#pragma unroll
    for (int i = 0; i < 2; i++)
#pragma unroll
        for (int jj = 0; jj < 4; jj++) qacc[i][jj] = 0.0f;

    int arow = co_blk + (l & 15);
    int qrow = 256 + (l & 15);
    u32 acolh = (u32)((l >> 4) << 4);

    for (int ch = 0; ch < 4; ch++) {
        int c0 = ch * 64;
#pragma unroll
        for (int e = 0; e < 17; e++) {
            int i = t + 256 * e;
            int row = i >> 4, f4 = i & 15;
            const float* src;
            if (row < 256)      src = wv + (size_t)row * NC + c0;
            else if (row < 264) src = wq + (size_t)(row - 256) * NC + c0;
            else                src = wk + (size_t)(row - 264) * NC + c0;
            float4 v4 = *(const float4*)(src + f4 * 4);
            u32 h0 = bf2(v4.x, v4.y), h1 = bf2(v4.z, v4.w);
            u32 l0 = bf2(v4.x - bflo(h0), v4.y - bfhi(h0));
            u32 l1 = bf2(v4.z - bflo(h1), v4.w - bfhi(h1));
            u32 off = (u32)(row * 128) + (u32)((f4 * 8) ^ ((row & 7) << 4));
            *(uint2*)(sm + PW_H + off) = make_uint2(h0, h1);
            *(uint2*)(sm + PW_L + off) = make_uint2(l0, l1);
        }
#pragma unroll
        for (int e = 0; e < 8; e++) {
            int i = t + 256 * e;
            int row = i >> 5, n4 = (i & 31) * 4;
            float4 v4 = *(const float4*)(x + ((size_t)b * NC + c0 + row) * NN + n0 + n4);
            u32 h0 = bf2(v4.x, v4.y), h1 = bf2(v4.z, v4.w);
            u32 l0 = bf2(v4.x - bflo(h0), v4.y - bfhi(h0));
            u32 l1 = bf2(v4.z - bflo(h1), v4.w - bfhi(h1));
            u32 off = (u32)(row * 256) + (u32)((n4 * 2) ^ ((row & 7) << 4));
            *(uint2*)(sm + PX_H + off) = make_uint2(h0, h1);
            *(uint2*)(sm + PX_L + off) = make_uint2(l0, l1);
        }
        __syncthreads();

#pragma unroll
        for (int kt = 0; kt < 4; kt++) {
            u32 kb = (u32)(kt * 32);
            u32 ah[4][4], al[4][4];
#pragma unroll
            for (int mt = 0; mt < 4; mt++) {
                int rr = arow + mt * 16;
                u32 ad = (u32)(rr * 128) + ((kb + acolh) ^ (u32)((rr & 7) << 4));
                ldmx4(sb + PW_H + ad, ah[mt][0], ah[mt][1], ah[mt][2], ah[mt][3]);
                ldmx4(sb + PW_L + ad, al[mt][0], al[mt][1], al[mt][2], al[mt][3]);
            }
#pragma unroll
            for (int nt = 0; nt < 8; nt++) {
                int cir = kt * 16 + (l & 15);
                u32 bd = sb + PX_H + (u32)(cir * 256)
                       + (u32)(((n_blk + nt * 8) * 2) ^ ((cir & 7) << 4));
                u32 b0, b1;
                ldmx2t(bd, b0, b1);
#pragma unroll
                for (int mt = 0; mt < 4; mt++) {
                    float* d = &acc[(mt * 8 + nt) * 4];
                    mma16816(d, ah[mt][0], ah[mt][1], ah[mt][2], ah[mt][3], b0, b1);
                    mma16816(d, al[mt][0], al[mt][1], al[mt][2], al[mt][3], b0, b1);
                }
            }
            {
                int rr = qrow;
                u32 ad = (u32)(rr * 128) + ((kb + acolh) ^ (u32)((rr & 7) << 4));
                u32 qh[4], ql[4];
                ldmx4(sb + PW_H + ad, qh[0], qh[1], qh[2], qh[3]);
                ldmx4(sb + PW_L + ad, ql[0], ql[1], ql[2], ql[3]);
                int cir = kt * 16 + (l & 15);
                u32 rswz = (u32)((cir & 7) << 4);
                u32 rbase = (u32)(cir * 256);
#pragma unroll
                for (int qi = 0; qi < 2; qi++) {
                    int qnt = 2 * w + qi;
                    u32 cbyte = (u32)((qnt * 8) * 2) ^ rswz;
                    u32 bh0, bh1, bl0, bl1;
                    ldmx2t(sb + PX_H + rbase + cbyte, bh0, bh1);
                    ldmx2t(sb + PX_L + rbase + cbyte, bl0, bl1);
                    mma16816(qacc[qi], qh[0], qh[1], qh[2], qh[3], bh0, bh1);
                    mma16816(qacc[qi], qh[0], qh[1], qh[2], qh[3], bl0, bl1);
                    mma16816(qacc[qi], ql[0], ql[1], ql[2], ql[3], bh0, bh1);
                }
            }
        }
        __syncthreads();
    }

    {
        int d_ = l >> 2;
        float bq_ = bq[d_], bk_ = bk[d_];
#pragma unroll
        for (int qi = 0; qi < 2; qi++) {
            int n_g = n0 + (2 * w + qi) * 8 + (l & 3) * 2;
            size_t e0 = ((size_t)b * NN + n_g) * ND + d_;
            g_q[e0]      = qacc[qi][0] + bq_;
            g_q[e0 + ND] = qacc[qi][1] + bq_;
            g_k[e0]      = qacc[qi][2] + bk_;
            g_k[e0 + ND] = qacc[qi][3] + bk_;
        }
    }

    {
        char* stg = sm + PSTAGE + w * 8192;  // [64 co][64 n] bf16, swizzled
#pragma unroll
        for (int mt = 0; mt < 4; mt++) {
            int r0 = mt * 16 + (l >> 2);
            float b0_ = sBV[co_blk + r0];
            float b1_ = sBV[co_blk + r0 + 8];
#pragma unroll
            for (int nt = 0; nt < 8; nt++) {
                const float* d = &acc[(mt * 8 + nt) * 4];
                u32 w0 = bf2(d[0] + b0_, d[1] + b0_);
                u32 w1 = bf2(d[2] + b1_, d[3] + b1_);
                u32 cb = (u32)(nt * 16 + (l & 3) * 4);
                *(u32*)(stg + r0 * 128 + (cb ^ ((r0 & 7) << 4))) = w0;
                *(u32*)(stg + (r0 + 8) * 128 + (cb ^ (((r0 + 8) & 7) << 4))) = w1;
            }
        }
    }
    __syncthreads();
#pragma unroll
    for (int e = 0; e < 16; e++) {
        int i = t + 256 * e;
        int co = i >> 4, chn = i & 15;
        int n = chn * 8;
        int wr = (co >> 6) | ((n >> 6) << 2);
        int cr = co & 63, nr = n & 63;
        float4 v4 = *(const float4*)(sm + PSTAGE + wr * 8192 + cr * 128
                                     + ((nr * 2) ^ ((cr & 7) << 4)));
        *(float4*)((void*)(g_v + ((size_t)b * NC + co) * NN + n0 + n)) = v4;
    }
}

// ---------------------------------------------------------------------------
// Kernel 2: flash attention, 512 threads / 16 warps (4 per SMSP).
// S via single-plane fp16 MMA (Q,K fp16); PV via bf16 MMA, ldmx4 B loads.
// One barrier per tile; P, K, V double buffered.
// S phase: warp covers rows (w&7)*16..+15, key cols (w>>3)*32..+31.
// PV phase: warp covers m_blk=(w&3)*32, c_blk=(w>>2)*64.
// ---------------------------------------------------------------------------
#define OFF_K   0                     // 2 x [64][16B] fp16 = 2048 B
#define OFF_P   2048                  // 2 x [128][64] bf16 = 32768 B
#define OFF_V   34816                 // 2 x [256][64] bf16 = 65536 B
#define OFF_RS  100352                // 2 x 128 f32 = 1024 B
#define FLASH_SMEM 101376

__global__ __launch_bounds__(512, 1) void flash_mma_kernel(
    const float* __restrict__ x,
    const float* __restrict__ gamma,
    float* __restrict__ out)
{
    extern __shared__ char sm[];
    u32 sb = smem_u32(sm);
    int t = threadIdx.x, l = t & 31, w = t >> 5;
    int b = blockIdx.y, m0 = blockIdx.x * BM;
    int m_blk = (w & 3) * 32, c_blk = (w >> 2) * 64;
    int r = l >> 2, c2 = (l & 3) * 2;
    int rowS = (w & 7) * 16 + r;          // S-phase row (this lane's quad)
    int colS = (w >> 3) * 32;             // S-phase key-col base

    // ---- Q fragments: single-plane fp16, log2e folded ----
    u32 qa0, qa1;
    const u32 zz = 0;
    {
        const float* qp = g_q + ((size_t)b * NN + m0 + rowS) * ND + c2;
        const float* qp2 = qp + 8 * ND;
        qa0 = f16x2(qp[0] * LOG2E, qp[1] * LOG2E);
        qa1 = f16x2(qp2[0] * LOG2E, qp2[1] * LOG2E);
    }

    float acc[64];
#pragma unroll
    for (int i = 0; i < 64; i++) acc[i] = 0.0f;
    float lsA = 0.0f, lsB = 0.0f;

    const __nv_bfloat16* vg = g_v + (size_t)b * NC * NN;

    u32 pbase = sb + OFF_P, vbase = sb + OFF_V;
    int arow  = m_blk + (l & 15);
    u32 aswz  = (u32)((l & 7) << 4);
    u32 acolh = (u32)((l >> 4) << 4);
    // PV B ldmx4 row: covers 16 c-rows (two n8 tiles) per load
    int brow4 = ((l >> 4) << 3) + (l & 7);
    u32 bkh   = (u32)(((l >> 3) & 1) << 4);

    float4 kA, kB;  // K register staging (threads 0..63)

    auto ldgK = [&](int j) {
        if (t < 64) {
            const float4* kp = (const float4*)(g_k + ((size_t)b * NN + j * BN2 + t) * ND);
            kA = kp[0]; kB = kp[1];
        }
    };
    auto stsK = [&](int kbuf) {
        if (t < 64) {
            uint4 kw;
            kw.x = f16x2(kA.x * LOG2E * 0.0f + kA.x, kA.y);  // plain pack
            kw.x = f16x2(kA.x, kA.y); kw.y = f16x2(kA.z, kA.w);
            kw.z = f16x2(kB.x, kB.y); kw.w = f16x2(kB.z, kB.w);
            *(uint4*)(sm + OFF_K + kbuf * 1024 + t * 16) = kw;
        }
    };
    auto loadV = [&](int j, int buf) {
        u32 vd = vbase + (u32)buf * 32768;
        const __nv_bfloat16* vsrc = vg + j * BN2;
#pragma unroll
        for (int e = 0; e < 4; e++) {
            int lin = e * 512 + t;
            int row = lin >> 3, c16 = lin & 7;
            u32 dof = (u32)(row * 128 + ((c16 * 16) ^ ((row & 7) << 4)));
            cpa16(vd + dof, vsrc + (size_t)row * NN + c16 * 8);
        }
        asm volatile("cp.async.commit_group;" ::: "memory");
    };
    // S phase for one tile -> P[pbuf], reads K[pbuf]
    auto sphase = [&](int pbuf) {
        u32 paxor = (u32)((rowS & 7) << 4);
        char* pd = sm + OFF_P + pbuf * 16384;
        char* prow0 = pd + rowS * 128;
        char* prow8 = prow0 + 8 * 128;
        u32 kbase = sb + OFF_K + (u32)pbuf * 1024;
        u32 colb  = (u32)(colS * 2 + (l & 3) * 4);
#pragma unroll
        for (int nt = 0; nt < 4; nt++) {
            u32 krow = (u32)(colS + nt * 8 + (l & 7));
            u32 b0, b1;
            ldmx2(kbase + krow * 16, b0, b1);
            float ds[4] = {0.f, 0.f, 0.f, 0.f};
            mma16816f(ds, qa0, qa1, zz, zz, b0, b1);
            u32 p01 = bf2(ex2f(ds[0]), ex2f(ds[1]));
            u32 p23 = bf2(ex2f(ds[2]), ex2f(ds[3]));
            lsA += bflo(p01) + bfhi(p01);
            lsB += bflo(p23) + bfhi(p23);
            u32 cbyte = (colb + (u32)(nt * 16)) ^ paxor;
            *(u32*)(prow0 + cbyte) = p01;
            *(u32*)(prow8 + cbyte) = p23;
        }
    };

    // ---- prologue: K0,V0 in; sphase(0); K1 staged ----
    ldgK(0); stsK(0); loadV(0, 0);
    ldgK(1);
    asm volatile("cp.async.wait_group 0;" ::: "memory");
    __syncthreads();                  // K0, V0 visible
    sphase(0);                        // P0 (buf 0)
    stsK(1);                          // K1 -> buf 1
    __syncthreads();                  // P0, K1 visible

    for (int j = 0; j < NTILES; j++) {
        int buf = j & 1;
        if (j + 2 < NTILES) ldgK(j + 2);
        if (j + 1 < NTILES) loadV(j + 1, buf ^ 1);

        // ---- PV MMA(j): reads P[buf], V[buf] ----
        u32 pb = pbase + (u32)buf * 16384;
        u32 vb = vbase + (u32)buf * 32768;
#pragma unroll
        for (int ks = 0; ks < 4; ks++) {
            u32 af[2][4];
#pragma unroll
            for (int mt = 0; mt < 2; mt++) {
                u32 ad = pb + (u32)((arow + mt * 16) * 128)
                       + (((u32)(ks * 32) + acolh) ^ aswz);
                ldmx4(ad, af[mt][0], af[mt][1], af[mt][2], af[mt][3]);
            }
#pragma unroll
            for (int ctp = 0; ctp < 4; ctp++) {
                int brow = c_blk + ctp * 16 + brow4;
                u32 bd = vb + (u32)(brow * 128)
                       + (((u32)(ks * 32) + bkh) ^ ((u32)(brow & 7) << 4));
                u32 b0, b1, b2, b3;
                ldmx4(bd, b0, b1, b2, b3);
#pragma unroll
                for (int mt = 0; mt < 2; mt++) {
                    mma16816(&acc[(mt * 8 + 2 * ctp) * 4],
                             af[mt][0], af[mt][1], af[mt][2], af[mt][3], b0, b1);
                    mma16816(&acc[(mt * 8 + 2 * ctp + 1) * 4],
                             af[mt][0], af[mt][1], af[mt][2], af[mt][3], b2, b3);
                }
            }
        }

        // ---- sphase(j+1): writes P[buf^1], reads K[buf^1] ----
        if (j + 1 < NTILES) sphase(buf ^ 1);
        // ---- stage K(j+2) into K[buf] ----
        if (j + 2 < NTILES) stsK(buf);

        asm volatile("cp.async.wait_group 0;" ::: "memory");
        __syncthreads();   // P(j+1), V(j+1), K(j+2) visible; P(j)/V(j) free
    }

    // ---- row sums: quad reduce, two col-halves, then invert ----
    lsA += __shfl_xor_sync(0xffffffffu, lsA, 1);
    lsA += __shfl_xor_sync(0xffffffffu, lsA, 2);
    lsB += __shfl_xor_sync(0xffffffffu, lsB, 1);
    lsB += __shfl_xor_sync(0xffffffffu, lsB, 2);
    float* rs = (float*)(sm + OFF_RS);
    if ((l & 3) == 0) {
        int hbase = (w >> 3) * 128;
        rs[hbase + rowS]     = lsA;
        rs[hbase + rowS + 8] = lsB;
    }
    __syncthreads();
    if (t < 128) rs[t] = 1.0f / (rs[t] + rs[t + 128]);
    __syncthreads();

    float gm = *gamma;

    // ---- Epilogue: out[b,c,m] = gamma * acc * inv[m] + x[b,c,m] ----
#pragma unroll
    for (int mt = 0; mt < 2; mt++) {
        int r0 = m_blk + mt * 16 + r;
        float s0 = gm * rs[r0];
        float s1 = gm * rs[r0 + 8];
#pragma unroll
        for (int ct = 0; ct < 8; ct++) {
            int c0 = c_blk + ct * 8 + (l & 3) * 2;
            const float* d = &acc[(mt * 8 + ct) * 4];
            size_t a0 = ((size_t)(b * NC + c0)) * NN + m0 + r0;
            size_t a1 = a0 + NN;
            out[a0]     = d[0] * s0 + x[a0];
            out[a1]     = d[1] * s0 + x[a1];
            out[a0 + 8] = d[2] * s1 + x[a0 + 8];
            out[a1 + 8] = d[3] * s1 + x[a1 + 8];
        }
    }
}

// ---------------------------------------------------------------------------
extern "C" void kernel_launch(void* const* d_in, const int* in_sizes, int n_in,
                              void* d_out, int out_size)
{
    const float* x     = (const float*)d_in[0];
    const float* wq    = (const float*)d_in[1];
    const float* bq    = (const float*)d_in[2];
    const float* wk    = (const float*)d_in[3];
    const float* bk    = (const float*)d_in[4];
    const float* wv    = (const float*)d_in[5];
    const float* bv    = (const float*)d_in[6];
    const float* gamma = (const float*)d_in[7];
    float* out = (float*)d_out;

    cudaFuncSetAttribute(proj_kernel,
                         cudaFuncAttributeMaxDynamicSharedMemorySize,
                         PROJ_SMEM);
    cudaFuncSetAttribute(flash_mma_kernel,
                         cudaFuncAttributeMaxDynamicSharedMemorySize,
                         FLASH_SMEM);

    proj_kernel<<<dim3(NN / 128, NB), 256, PROJ_SMEM>>>(x, wq, bq, wk, bk, wv, bv);
    flash_mma_kernel<<<dim3(NN / BM, NB), 512, FLASH_SMEM>>>(x, gamma, out);
}